// round 2
// baseline (speedup 1.0000x reference)
#include <cuda_runtime.h>
#include <cstdint>

// ExpandMask: x [B=64, 1, L=262144] f32  ->  out [B, 1, 2L] float (0.0/1.0)
//   out[2i]   = (x[i-1] + x[i] + x[i+1] > 0.5) ? 1 : 0   (zero taps outside row)
//   out[2i+1] = (x[i]   + x[i+1]        > 0.5) ? 1 : 0
//
// Memory-bound streaming kernel: each thread handles 8 inputs (2x float4 load,
// 2 scalar halo loads that hit L1/L2) and writes 16 output floats (4x STG.128).

static constexpr int L = 262144;              // input row length
static constexpr int ELEMS_PER_THREAD = 8;    // inputs per thread
static constexpr int THREADS_PER_ROW = L / ELEMS_PER_THREAD;  // 32768

__global__ void __launch_bounds__(256) expand_mask_kernel(
    const float* __restrict__ x, float4* __restrict__ out)
{
    const int tid = blockIdx.x * blockDim.x + threadIdx.x;
    const int row = tid / THREADS_PER_ROW;
    const int tr  = tid - row * THREADS_PER_ROW;   // thread index within row

    const int ibase = row * L + tr * ELEMS_PER_THREAD;

    const float4 v0 = *reinterpret_cast<const float4*>(x + ibase);
    const float4 v1 = *reinterpret_cast<const float4*>(x + ibase + 4);

    // Halo taps (zero at row boundaries). Interior threads: L1/L2 hits.
    const float left  = (tr == 0)                    ? 0.0f : __ldg(x + ibase - 1);
    const float right = (tr == THREADS_PER_ROW - 1)  ? 0.0f : __ldg(x + ibase + 8);

    float a[10];
    a[0] = left;
    a[1] = v0.x; a[2] = v0.y; a[3] = v0.z; a[4] = v0.w;
    a[5] = v1.x; a[6] = v1.y; a[7] = v1.z; a[8] = v1.w;
    a[9] = right;

    // 16 output floats: o[2k]   = (a[k] + a[k+1] + a[k+2] > 0.5)
    //                   o[2k+1] = (a[k+1] + a[k+2]        > 0.5)   k = 0..7
    // output float index base = row*2L + tr*16, 16B-aligned -> 4x float4
    const long ovec = ((long)row * 2 * L + (long)tr * 16) / 4;  // float4 index

    #pragma unroll
    for (int q = 0; q < 4; q++) {
        // float4 q covers inputs k = 2q, 2q+1
        const int k0 = 2 * q;
        const float ps0 = a[k0 + 1] + a[k0 + 2];
        const float ps1 = a[k0 + 2] + a[k0 + 3];
        float4 o;
        o.x = (a[k0]     + ps0) > 0.5f ? 1.0f : 0.0f;
        o.y =               ps0  > 0.5f ? 1.0f : 0.0f;
        o.z = (a[k0 + 1] + ps1) > 0.5f ? 1.0f : 0.0f;
        o.w =               ps1  > 0.5f ? 1.0f : 0.0f;
        out[ovec + q] = o;
    }
}

extern "C" void kernel_launch(void* const* d_in, const int* in_sizes, int n_in,
                              void* d_out, int out_size)
{
    const float* x = (const float*)d_in[0];
    float4* out = (float4*)d_out;

    const int n_in_elems = in_sizes[0];                 // 64 * 262144
    const int total_threads = n_in_elems / ELEMS_PER_THREAD;
    const int block = 256;
    const int grid = (total_threads + block - 1) / block;

    expand_mask_kernel<<<grid, block>>>(x, out);
}

// round 3
// speedup vs baseline: 1.0406x; 1.0406x over previous
#include <cuda_runtime.h>
#include <cstdint>

// ExpandMask: x [B=64, 1, L=262144] f32  ->  out [B, 1, 2L] float (0.0/1.0)
//   out[2i]   = (x[i-1] + x[i] + x[i+1] > 0.5) ? 1 : 0   (zero taps outside row)
//   out[2i+1] = (x[i]   + x[i+1]        > 0.5) ? 1 : 0
//
// R3: halo taps come from warp shuffles (warp covers 256 contiguous floats);
// only lane 0 / lane 31 issue a 4B halo load. Streaming cache hints on the
// main load/store paths.

static constexpr int L = 262144;              // input row length
static constexpr int ELEMS_PER_THREAD = 8;    // inputs per thread
static constexpr int THREADS_PER_ROW = L / ELEMS_PER_THREAD;  // 32768

__global__ void __launch_bounds__(256) expand_mask_kernel(
    const float* __restrict__ x, float4* __restrict__ out)
{
    const int tid  = blockIdx.x * blockDim.x + threadIdx.x;
    const int row  = tid / THREADS_PER_ROW;
    const int tr   = tid - row * THREADS_PER_ROW;   // thread index within row
    const int lane = threadIdx.x & 31;

    const int ibase = row * L + tr * ELEMS_PER_THREAD;

    const float4 v0 = __ldcs(reinterpret_cast<const float4*>(x + ibase));
    const float4 v1 = __ldcs(reinterpret_cast<const float4*>(x + ibase + 4));

    float a[10];
    a[1] = v0.x; a[2] = v0.y; a[3] = v0.z; a[4] = v0.w;
    a[5] = v1.x; a[6] = v1.y; a[7] = v1.z; a[8] = v1.w;

    // Halos: previous lane's last element / next lane's first element.
    // Warps never straddle rows (32768 threads per row, warp-aligned).
    float left  = __shfl_up_sync(0xffffffffu, a[8], 1);
    float right = __shfl_down_sync(0xffffffffu, a[1], 1);
    if (lane == 0)
        left  = (tr == 0) ? 0.0f : __ldg(x + ibase - 1);
    if (lane == 31)
        right = (tr == THREADS_PER_ROW - 1) ? 0.0f : __ldg(x + ibase + 8);
    a[0] = left;
    a[9] = right;

    // 16 output floats: o[2k]   = (a[k] + a[k+1] + a[k+2] > 0.5)
    //                   o[2k+1] = (a[k+1] + a[k+2]        > 0.5)   k = 0..7
    const long ovec = ((long)row * 2 * L + (long)tr * 16) / 4;  // float4 index

    #pragma unroll
    for (int q = 0; q < 4; q++) {
        const int k0 = 2 * q;
        const float ps0 = a[k0 + 1] + a[k0 + 2];
        const float ps1 = a[k0 + 2] + a[k0 + 3];
        float4 o;
        o.x = (a[k0]     + ps0) > 0.5f ? 1.0f : 0.0f;
        o.y =               ps0  > 0.5f ? 1.0f : 0.0f;
        o.z = (a[k0 + 1] + ps1) > 0.5f ? 1.0f : 0.0f;
        o.w =               ps1  > 0.5f ? 1.0f : 0.0f;
        __stcs(&out[ovec + q], o);
    }
}

extern "C" void kernel_launch(void* const* d_in, const int* in_sizes, int n_in,
                              void* d_out, int out_size)
{
    const float* x = (const float*)d_in[0];
    float4* out = (float4*)d_out;

    const int n_in_elems = in_sizes[0];                 // 64 * 262144
    const int total_threads = n_in_elems / ELEMS_PER_THREAD;
    const int block = 256;
    const int grid = (total_threads + block - 1) / block;

    expand_mask_kernel<<<grid, block>>>(x, out);
}